// round 13
// baseline (speedup 1.0000x reference)
#include <cuda_runtime.h>

#define NC 19
#define BB 8
#define HH 512
#define WIDTH 512
#define HW (HH*WIDTH)
#define WW 16
#define HALO 20
#define STRIP 256
#define RB (STRIP + 2*HALO)   // 296 window rows
#define NSTRIP (HH/STRIP)     // 2
#define NBLK (BB*NC*NSTRIP)   // 304
#define NWORDS (RB*WW)        // 4736 real words
#define IWORDS (STRIP*WW)     // 4096 interior words
#define TPB 512
#define NSLOT 10
#define PADW (NSLOT*TPB)      // 5120 padded words (fake rows 296..319 stay zero)
#define HBSZ (PADW + 32)      // 16-word zero pad both ends -> no boundary guards
#define SMEMSZ ((2*HBSZ + 4*IWORDS)*4)   // 106752 B -> 2 CTA/SM
#define NB3 1024              // k_loss blocks (8 px/thread)

// Scratch (static device globals; allocation-free)
__device__ unsigned       g_bits[(size_t)BB*NC*HH*WW];  // ~5 MB packed class masks
__device__ unsigned char  g_dist[(size_t)BB*NC*HW];     // 40 MB distances (0..20)
__device__ unsigned       g_t4[(size_t)NBLK*IWORDS];    // rare 5th first-set plane
__device__ float          g_part[NB3];

// Fast exp on the FMA pipe (|rel err| ~3e-6)
__device__ __forceinline__ float fexp(float x) {
    float y = x * 1.4426950408889634f;
    y = fmaxf(y, -80.0f);
    float z = y + 12582912.0f;
    int   n = __float_as_int(z) - 0x4B400000;
    float f = y - (z - 12582912.0f);
    float p =          1.3333558e-3f;
    p = fmaf(p, f, 9.6181291e-3f);
    p = fmaf(p, f, 5.5504109e-2f);
    p = fmaf(p, f, 2.4022651e-1f);
    p = fmaf(p, f, 6.9314718e-1f);
    p = fmaf(p, f, 1.0f);
    return __int_as_float(__float_as_int(p) + (n << 23));
}

// K0: bit-pack per-class masks via warp ballots (target int32)
__global__ void k_bits(const int* __restrict__ tgt) {
    int g    = blockIdx.x * blockDim.x + threadIdx.x;
    int lane = g & 31;
    int wid  = g >> 5;
    int ww   = wid & 15;
    int h    = (wid >> 4) & 511;
    int b    = wid >> 13;
    int lab  = tgt[(size_t)(b * HH + h) * WIDTH + ww * 32 + lane];
    unsigned my = 0;
#pragma unroll
    for (int c = 0; c < NC; ++c) {
        unsigned bal = __ballot_sync(0xffffffffu, lab == c);
        if (lane == c) my = bal;
    }
    if (lane < NC)
        g_bits[((size_t)(b * NC + lane) * HH + h) * WW + ww] = my;
}

// K1: single-barrier fused dilation. Warp owns 20 contiguous rows; mask lives
// in registers; horizontal neighbor words come from adjacent lanes via shfl;
// vertical neighbors via double-buffered H rows in smem. dist = first_set - m0.
__global__ void __launch_bounds__(TPB, 2) k_dilate() {
    extern __shared__ unsigned sh[];
    unsigned* bufA = sh + 16;              // logical [0,PADW); zero pads outside
    unsigned* bufB = sh + HBSZ + 16;
    unsigned* T    = sh + 2 * HBSZ;        // 4*IWORDS first-set bit planes

    int blk = blockIdx.x;
    int s   = blk & (NSTRIP - 1);
    int t2  = blk >> 1;
    int c   = t2 % NC;
    int b   = t2 / NC;
    int tid = threadIdx.x;
    int lane = tid & 31;
    int idx0 = (tid >> 5) * (NSLOT * 32) + lane;
    int k    = lane & 15;                  // word-in-row (idx&15 == lane&15)
    int g0  = s * STRIP - HALO;

    const unsigned* mbase = g_bits + (size_t)(b * NC + c) * HH * WW;
    unsigned* t4 = g_t4 + (size_t)blk * IWORDS;
    for (int i = tid; i < 2 * HBSZ; i += TPB) sh[i] = 0u;
    for (int i = tid; i < 4 * IWORDS; i += TPB) T[i] = 0u;
    for (int i = tid; i < IWORDS; i += TPB) t4[i] = 0u;

    unsigned mreg[NSLOT], G[NSLOT], um[NSLOT];
    bool intr[NSLOT];
#pragma unroll
    for (int j = 0; j < NSLOT; ++j) {
        int idx = idx0 + j * 32;
        int r = idx >> 4;
        int g = g0 + r;
        bool in = (idx < NWORDS) && (g >= 0) && (g < HH);
        um[j]   = in ? 0xFFFFFFFFu : 0u;
        intr[j] = (r >= HALO) && (r < RB - HALO);
        mreg[j] = in ? __ldg(mbase + (size_t)g * WW + k) : 0u;
    }
    __syncthreads();   // zero-fill complete before H writes

    // initial H = m0 | G(m0)  (horizontal via in-warp shuffles)
#pragma unroll
    for (int j = 0; j < NSLOT; ++j) {
        unsigned m  = mreg[j];
        unsigned lw = __shfl_up_sync(0xffffffffu, m, 1);   lw = (k > 0)  ? lw : 0u;
        unsigned rw = __shfl_down_sync(0xffffffffu, m, 1); rw = (k < 15) ? rw : 0u;
        unsigned g = __funnelshift_l(lw, m, 1) | __funnelshift_r(m, rw, 1);
        G[j] = g;
        bufA[idx0 + j * 32] = m | g;
    }
    __syncthreads();

    unsigned* pc = bufA;
    unsigned* pn = bufB;
    for (int it = 0; it < 20; ++it) {
        unsigned satin = 0xFFFFFFFFu;
#pragma unroll
        for (int j = 0; j < NSLOT; ++j) {
            int idx = idx0 + j * 32;
            unsigned up = pc[idx - WW];
            unsigned dn = pc[idx + WW];
            unsigned nv = (up | dn | G[j]) & um[j];
            if (intr[j]) {
                satin &= nv;
                int pi = idx - HALO * WW;
                if (it == 0) {
                    T[pi] = nv;            // first-set = 1 for all of m_1
                } else {
                    unsigned nb = nv & ~mreg[j];
                    if (nb) {
                        int jv = it + 1;
                        if (jv & 1)  T[pi]              |= nb;
                        if (jv & 2)  T[IWORDS + pi]     |= nb;
                        if (jv & 4)  T[2 * IWORDS + pi] |= nb;
                        if (jv & 8)  T[3 * IWORDS + pi] |= nb;
                        if (jv & 16) t4[pi]             |= nb;
                    }
                }
            }
            // next iteration's horizontal part from nv (uniform across warp)
            unsigned lw = __shfl_up_sync(0xffffffffu, nv, 1);   lw = (k > 0)  ? lw : 0u;
            unsigned rw = __shfl_down_sync(0xffffffffu, nv, 1); rw = (k < 15) ? rw : 0u;
            unsigned gn = __funnelshift_l(lw, nv, 1) | __funnelshift_r(nv, rw, 1);
            pn[idx] = nv | gn;
            mreg[j] = nv;
            G[j] = gn;
        }
        int any = __syncthreads_or((int)(satin != 0xFFFFFFFFu));
        unsigned* t = pc; pc = pn; pn = t;
        if (!any) break;   // all interior words saturated == fixed point
    }

    // finalize: store final mask, then byte = mf ? (first_set - m0bit) : 20
#pragma unroll
    for (int j = 0; j < NSLOT; ++j) bufA[idx0 + j * 32] = mreg[j];
    __syncthreads();

    unsigned* obase = (unsigned*)(g_dist + ((size_t)(b * NC + c) * HH + s * STRIP) * WIDTH);
    const unsigned* m0base = mbase + (size_t)(s * STRIP) * WW;
    for (int q = tid; q < STRIP * WIDTH / 4; q += TPB) {
        int r  = q >> 7;
        int u  = q & 127;
        int w  = u >> 3;
        int jb = (u & 7) * 4;
        int pi = r * WW + w;
        unsigned mf = bufA[(r + HALO) * WW + w];
        unsigned m0 = __ldg(m0base + r * WW + w);
        unsigned t0 = T[pi], t1 = T[IWORDS + pi], t2p = T[2 * IWORDS + pi],
                 t3 = T[3 * IWORDS + pi], tt4 = t4[pi];
        unsigned out = 0;
#pragma unroll
        for (int jj = 0; jj < 4; ++jj) {
            int j = jb + jj;
            int jset = (int)((t0 >> j) & 1u) + (int)(((t1 >> j) & 1u) << 1)
                     + (int)(((t2p >> j) & 1u) << 2) + (int)(((t3 >> j) & 1u) << 3)
                     + (int)(((tt4 >> j) & 1u) << 4);
            int v = ((mf >> j) & 1u) ? (jset - (int)((m0 >> j) & 1u)) : 20;
            out |= (unsigned)v << (jj * 8);
        }
        obase[q] = out;
    }
}

// K2: fused softmax + distance dot; 8 pixels/thread (2 independent quads)
__global__ void k_loss(const float* __restrict__ pred) {
    __shared__ float red[8];
    int g = blockIdx.x * 256 + threadIdx.x;   // 0..262143
    float acc = 0.f;
#pragma unroll
    for (int h = 0; h < 2; ++h) {
        int q  = g + h * 262144;              // quad index (total 524288)
        int b  = q >> 16;
        int hw = (q & 65535) * 4;
        const float4* p  = (const float4*)(pred   + (size_t)b * NC * HW + hw);
        const uchar4* dp = (const uchar4*)(g_dist + (size_t)b * NC * HW + hw);
        float se0 = 0.f, se1 = 0.f, se2 = 0.f, se3 = 0.f;
        float sd0 = 0.f, sd1 = 0.f, sd2 = 0.f, sd3 = 0.f;
#pragma unroll
        for (int c = 0; c < NC; ++c) {
            float4 v = __ldg(p + (size_t)c * (HW / 4));
            uchar4 d = __ldg(dp + (size_t)c * (HW / 4));
            float e0 = fexp(v.x), e1 = fexp(v.y), e2 = fexp(v.z), e3 = fexp(v.w);
            se0 += e0; se1 += e1; se2 += e2; se3 += e3;
            sd0 = fmaf(e0, (float)d.x, sd0);
            sd1 = fmaf(e1, (float)d.y, sd1);
            sd2 = fmaf(e2, (float)d.z, sd2);
            sd3 = fmaf(e3, (float)d.w, sd3);
        }
        acc += __fdividef(sd0, se0) + __fdividef(sd1, se1)
             + __fdividef(sd2, se2) + __fdividef(sd3, se3);
    }
#pragma unroll
    for (int o = 16; o; o >>= 1) acc += __shfl_down_sync(0xffffffffu, acc, o);
    int tid = threadIdx.x;
    if ((tid & 31) == 0) red[tid >> 5] = acc;
    __syncthreads();
    if (tid < 8) {
        float x = red[tid];
#pragma unroll
        for (int o = 4; o; o >>= 1) x += __shfl_down_sync(0x000000ffu, x, o);
        if (tid == 0) g_part[blockIdx.x] = x;
    }
}

// K3: deterministic final reduction -> mean
__global__ void k_reduce(float* __restrict__ out) {
    __shared__ float red[32];
    int tid = threadIdx.x;
    float v = (tid < NB3) ? g_part[tid] : 0.f;
#pragma unroll
    for (int o = 16; o; o >>= 1) v += __shfl_down_sync(0xffffffffu, v, o);
    if ((tid & 31) == 0) red[tid >> 5] = v;
    __syncthreads();
    if (tid < 32) {
        float x = red[tid];
#pragma unroll
        for (int o = 16; o; o >>= 1) x += __shfl_down_sync(0xffffffffu, x, o);
        if (tid == 0) out[0] = x * (1.0f / ((float)BB * NC * HW));
    }
}

extern "C" void kernel_launch(void* const* d_in, const int* in_sizes, int n_in,
                              void* d_out, int out_size) {
    (void)in_sizes; (void)n_in; (void)out_size;
    const float* pred = (const float*)d_in[0];
    const int*   tgt  = (const int*)d_in[1];

    cudaFuncSetAttribute(k_dilate, cudaFuncAttributeMaxDynamicSharedMemorySize, SMEMSZ);

    k_bits<<<8192, 256>>>(tgt);
    k_dilate<<<NBLK, TPB, SMEMSZ>>>();
    k_loss<<<NB3, 256>>>(pred);
    k_reduce<<<1, 1024>>>((float*)d_out);
}

// round 14
// speedup vs baseline: 1.2401x; 1.2401x over previous
#include <cuda_runtime.h>

#define NC 19
#define BB 8
#define HH 512
#define WIDTH 512
#define HW (HH*WIDTH)
#define WW 16
#define HALO 20
#define STRIP 256
#define RB (STRIP + 2*HALO)   // 296 window rows
#define NSTRIP (HH/STRIP)     // 2
#define NBLK (BB*NC*NSTRIP)   // 304
#define NWORDS (RB*WW)        // 4736
#define IWORDS (STRIP*WW)     // 4096 interior words
#define TPB 512
#define NSLOT 10              // ceil(4736/512)
#define SMEMSZ ((NWORDS*2 + IWORDS*4)*4)   // 103424 B -> 2 CTA/SM
#define NB3 2048              // k_loss blocks (4 px/thread)

// Scratch (static device globals; allocation-free)
__device__ unsigned       g_bits[(size_t)BB*NC*HH*WW];  // ~5 MB packed class masks
__device__ unsigned char  g_dist[(size_t)BB*NC*HW];     // 40 MB distances (0..20)
__device__ unsigned       g_t4[(size_t)NBLK*IWORDS];    // rare 5th first-set plane
__device__ float          g_part[NB3];                  // per-block loss partials
__device__ unsigned       g_ctr;                        // last-block-done counter (zero-init)

// K0: bit-pack per-class masks via warp ballots (target int32)
__global__ void k_bits(const int* __restrict__ tgt) {
    int g    = blockIdx.x * blockDim.x + threadIdx.x;
    int lane = g & 31;
    int wid  = g >> 5;
    int ww   = wid & 15;
    int h    = (wid >> 4) & 511;
    int b    = wid >> 13;
    int lab  = tgt[(size_t)(b * HH + h) * WIDTH + ww * 32 + lane];
    unsigned my = 0;
#pragma unroll
    for (int c = 0; c < NC; ++c) {
        unsigned bal = __ballot_sync(0xffffffffu, lab == c);
        if (lane == c) my = bal;
    }
    if (lane < NC)
        g_bits[((size_t)(b * NC + lane) * HH + h) * WW + ww] = my;
}

// K1: two-phase bitwise dilation (exact R8 body, the validated 119us version).
// First-set planes give dist = first_set - m0bit; zero-clamped padding;
// interior saturation exit; per-thread done freeze.
__global__ void __launch_bounds__(TPB, 2) k_dilate() {
    extern __shared__ unsigned sh[];
    unsigned* M  = sh;                    // NWORDS  current mask
    unsigned* Hb = sh + NWORDS;           // NWORDS  H = m|shl|shr rows
    unsigned* T  = sh + 2 * NWORDS;       // 4*IWORDS first-set bit planes (bits 0..3)

    int blk = blockIdx.x;
    int s   = blk & (NSTRIP - 1);
    int t2  = blk >> 1;
    int c   = t2 % NC;
    int b   = t2 / NC;
    int tid = threadIdx.x;
    int g0  = s * STRIP - HALO;

    const unsigned* mbase = g_bits + (size_t)(b * NC + c) * HH * WW;
    unsigned* t4 = g_t4 + (size_t)blk * IWORDS;
    for (int i = tid; i < NWORDS; i += TPB) {
        int g = g0 + (i >> 4);
        M[i]  = (g >= 0 && g < HH) ? mbase[(size_t)g * WW + (i & 15)] : 0u;
        Hb[i] = 0u;                        // stable 0 for never-written rows
    }
    for (int i = tid; i < 4 * IWORDS; i += TPB) T[i] = 0u;
    for (int i = tid; i < IWORDS; i += TPB) t4[i] = 0u;
    __syncthreads();

    unsigned mreg[NSLOT], G[NSLOT];
    bool inimg[NSLOT], act[NSLOT];
    bool allout = true;
#pragma unroll
    for (int j = 0; j < NSLOT; ++j) {
        int idx = j * TPB + tid;
        act[j] = (idx < NWORDS);
        mreg[j] = act[j] ? M[idx] : 0u;
        int g = g0 + (idx >> 4);
        inimg[j] = act[j] && (g >= 0) && (g < HH);
        allout &= !inimg[j];
    }
    bool done = allout;
    bool fixpend = false;

    for (int it = 0; it < 20; ++it) {
        // phase A: H = m | shl(m) | shr(m)
        if (!done) {
#pragma unroll
            for (int j = 0; j < NSLOT; ++j) {
                if (!act[j]) continue;
                int idx = j * TPB + tid;
                int k = idx & 15;
                unsigned m  = mreg[j];
                unsigned lw = (k > 0)  ? M[idx - 1] : 0u;
                unsigned rw = (k < 15) ? M[idx + 1] : 0u;
                unsigned g = __funnelshift_l(lw, m, 1) | __funnelshift_r(m, rw, 1);
                G[j] = g;
                Hb[idx] = m | g;
            }
        } else if (fixpend) {
#pragma unroll
            for (int j = 0; j < NSLOT; ++j)
                if (inimg[j]) Hb[j * TPB + tid] = mreg[j];
            fixpend = false;
        }
        __syncthreads();
        // phase B: nv = (H(up) | H(dn) | G) clamped outside the image
        int notsat = 0;
        if (!done) {
            unsigned sat = 0xFFFFFFFFu;
#pragma unroll
            for (int j = 0; j < NSLOT; ++j) {
                if (!act[j]) continue;
                int idx = j * TPB + tid;
                int r = idx >> 4;
                unsigned up = (r > 0)      ? Hb[idx - WW] : 0u;
                unsigned dn = (r < RB - 1) ? Hb[idx + WW] : 0u;
                unsigned nv = inimg[j] ? (up | dn | G[j]) : 0u;
                unsigned m  = mreg[j];
                bool interior = (r >= HALO) && (r < RB - HALO);
                if (interior) {
                    sat &= nv;
                    int pi = idx - HALO * WW;
                    if (it == 0) {
                        T[pi] = nv;        // first-set=1 for all of m_1
                    } else {
                        unsigned nb = nv & ~m;
                        if (nb) {
                            int jv = it + 1;
                            if (jv & 1)  T[pi]              |= nb;
                            if (jv & 2)  T[IWORDS + pi]     |= nb;
                            if (jv & 4)  T[2 * IWORDS + pi] |= nb;
                            if (jv & 8)  T[3 * IWORDS + pi] |= nb;
                            if (jv & 16) t4[pi]             |= nb;
                        }
                    }
                }
                mreg[j] = nv;
                M[idx] = nv;
            }
            notsat = (int)(sat != 0xFFFFFFFFu);
            if (!notsat) { done = true; fixpend = true; }
        }
        int any = __syncthreads_or(notsat);
        if (!any) break;   // all interior words saturated == fixed point
    }

    // finalize: byte = mf ? (first_set - m0bit) : 20 ; coalesced u32 stores
    unsigned* obase = (unsigned*)(g_dist + ((size_t)(b * NC + c) * HH + s * STRIP) * WIDTH);
    const unsigned* m0base = mbase + (size_t)(s * STRIP) * WW;
    for (int q = tid; q < STRIP * WIDTH / 4; q += TPB) {
        int r  = q >> 7;
        int u  = q & 127;
        int w  = u >> 3;
        int jb = (u & 7) * 4;
        int pi = r * WW + w;
        unsigned mf = M[(r + HALO) * WW + w];
        unsigned m0 = __ldg(m0base + r * WW + w);
        unsigned t0 = T[pi], t1 = T[IWORDS + pi], t2p = T[2 * IWORDS + pi],
                 t3 = T[3 * IWORDS + pi], tt4 = t4[pi];
        unsigned out = 0;
#pragma unroll
        for (int jj = 0; jj < 4; ++jj) {
            int j = jb + jj;
            int jset = (int)((t0 >> j) & 1u) + (int)(((t1 >> j) & 1u) << 1)
                     + (int)(((t2p >> j) & 1u) << 2) + (int)(((t3 >> j) & 1u) << 3)
                     + (int)(((tt4 >> j) & 1u) << 4);
            int v = ((mf >> j) & 1u) ? (jset - (int)((m0 >> j) & 1u)) : 20;
            out |= (unsigned)v << (jj * 8);
        }
        obase[q] = out;
    }
}

// K2: fused softmax + distance dot (4 px/thread, MUFU exp) + last-block-done
// deterministic final reduction (fixed-order read of all partials).
__global__ void k_loss(const float* __restrict__ pred, float* __restrict__ out) {
    __shared__ float red[8];
    __shared__ bool amlast;
    int g   = blockIdx.x * 256 + threadIdx.x;   // pixel-quad index
    int b   = g >> 16;
    int hw  = (g & 65535) * 4;
    const float4* p  = (const float4*)(pred   + (size_t)b * NC * HW + hw);
    const uchar4* dp = (const uchar4*)(g_dist + (size_t)b * NC * HW + hw);
    float se0 = 0.f, se1 = 0.f, se2 = 0.f, se3 = 0.f;
    float sd0 = 0.f, sd1 = 0.f, sd2 = 0.f, sd3 = 0.f;
#pragma unroll
    for (int c = 0; c < NC; ++c) {
        float4 v = __ldg(p + (size_t)c * (HW / 4));
        uchar4 d = __ldg(dp + (size_t)c * (HW / 4));
        float e0 = __expf(v.x), e1 = __expf(v.y), e2 = __expf(v.z), e3 = __expf(v.w);
        se0 += e0; se1 += e1; se2 += e2; se3 += e3;
        sd0 = fmaf(e0, (float)d.x, sd0);
        sd1 = fmaf(e1, (float)d.y, sd1);
        sd2 = fmaf(e2, (float)d.z, sd2);
        sd3 = fmaf(e3, (float)d.w, sd3);
    }
    float acc = __fdividef(sd0, se0) + __fdividef(sd1, se1)
              + __fdividef(sd2, se2) + __fdividef(sd3, se3);
#pragma unroll
    for (int o = 16; o; o >>= 1) acc += __shfl_down_sync(0xffffffffu, acc, o);
    int tid = threadIdx.x;
    if ((tid & 31) == 0) red[tid >> 5] = acc;
    __syncthreads();
    if (tid < 8) {
        float x = red[tid];
#pragma unroll
        for (int o = 4; o; o >>= 1) x += __shfl_down_sync(0x000000ffu, x, o);
        if (tid == 0) g_part[blockIdx.x] = x;
    }
    // last-block-done: deterministic final reduction (fixed read order)
    if (tid == 0) {
        __threadfence();
        amlast = (atomicAdd(&g_ctr, 1u) == NB3 - 1);
    }
    __syncthreads();
    if (amlast) {
        __threadfence();
        float v = 0.f;
#pragma unroll
        for (int i = 0; i < NB3 / 256; ++i) v += g_part[tid + i * 256];
#pragma unroll
        for (int o = 16; o; o >>= 1) v += __shfl_down_sync(0xffffffffu, v, o);
        if ((tid & 31) == 0) red[tid >> 5] = v;
        __syncthreads();
        if (tid < 8) {
            float x = red[tid];
#pragma unroll
            for (int o = 4; o; o >>= 1) x += __shfl_down_sync(0x000000ffu, x, o);
            if (tid == 0) {
                out[0] = x * (1.0f / ((float)BB * NC * HW));
                g_ctr = 0;                 // reset for next graph replay
            }
        }
    }
}

extern "C" void kernel_launch(void* const* d_in, const int* in_sizes, int n_in,
                              void* d_out, int out_size) {
    (void)in_sizes; (void)n_in; (void)out_size;
    const float* pred = (const float*)d_in[0];
    const int*   tgt  = (const int*)d_in[1];

    cudaFuncSetAttribute(k_dilate, cudaFuncAttributeMaxDynamicSharedMemorySize, SMEMSZ);

    k_bits<<<8192, 256>>>(tgt);
    k_dilate<<<NBLK, TPB, SMEMSZ>>>();
    k_loss<<<NB3, 256>>>(pred, (float*)d_out);
}

// round 15
// speedup vs baseline: 1.2630x; 1.0184x over previous
#include <cuda_runtime.h>

#define NC 19
#define BB 8
#define HH 512
#define WIDTH 512
#define HW (HH*WIDTH)
#define WW 16
#define HALO 20
#define STRIP 256
#define RB (STRIP + 2*HALO)   // 296 window rows
#define NSTRIP (HH/STRIP)     // 2
#define NBLK (BB*NC*NSTRIP)   // 304
#define NWORDS (RB*WW)        // 4736
#define IWORDS (STRIP*WW)     // 4096 interior words
#define TPB 512
#define NSLOT 10              // ceil(4736/512)
#define SMEMSZ ((NWORDS*2 + IWORDS*4)*4)   // 103424 B -> 2 CTA/SM
#define NB3 2048              // k_loss blocks (4 px/thread)

// Scratch (static device globals; allocation-free)
__device__ unsigned       g_bits[(size_t)BB*NC*HH*WW];  // ~5 MB packed class masks
__device__ unsigned char  g_dist[(size_t)BB*NC*HW];     // 40 MB distances (0..20)
__device__ unsigned       g_t4[(size_t)NBLK*IWORDS];    // rare 5th first-set plane
__device__ float          g_part[NB3];                  // per-block loss partials
__device__ unsigned       g_ctr;                        // last-block-done counter (zero-init)

// K0: bit-pack per-class masks via 5 bit-plane ballots (labels are 5-bit).
// Class-c word = AND_i (B_i XOR e_i), e_i = (c>>i&1) ? 0 : ~0.
__global__ void k_bits(const int* __restrict__ tgt) {
    int g    = blockIdx.x * blockDim.x + threadIdx.x;
    int lane = g & 31;
    int wid  = g >> 5;
    int ww   = wid & 15;
    int h    = (wid >> 4) & 511;
    int b    = wid >> 13;
    int lab  = tgt[(size_t)(b * HH + h) * WIDTH + ww * 32 + lane];
    unsigned B0 = __ballot_sync(0xffffffffu, lab & 1);
    unsigned B1 = __ballot_sync(0xffffffffu, lab & 2);
    unsigned B2 = __ballot_sync(0xffffffffu, lab & 4);
    unsigned B3 = __ballot_sync(0xffffffffu, lab & 8);
    unsigned B4 = __ballot_sync(0xffffffffu, lab & 16);
    if (lane < NC) {
        int c = lane;
        unsigned w = (B0 ^ ((c & 1)  ? 0u : 0xFFFFFFFFu))
                   & (B1 ^ ((c & 2)  ? 0u : 0xFFFFFFFFu))
                   & (B2 ^ ((c & 4)  ? 0u : 0xFFFFFFFFu))
                   & (B3 ^ ((c & 8)  ? 0u : 0xFFFFFFFFu))
                   & (B4 ^ ((c & 16) ? 0u : 0xFFFFFFFFu));
        g_bits[((size_t)(b * NC + c) * HH + h) * WW + ww] = w;
    }
}

// K1: two-phase bitwise dilation (exact R8 body, the validated version).
// First-set planes give dist = first_set - m0bit; zero-clamped padding;
// interior saturation exit; per-thread done freeze.
__global__ void __launch_bounds__(TPB, 2) k_dilate() {
    extern __shared__ unsigned sh[];
    unsigned* M  = sh;                    // NWORDS  current mask
    unsigned* Hb = sh + NWORDS;           // NWORDS  H = m|shl|shr rows
    unsigned* T  = sh + 2 * NWORDS;       // 4*IWORDS first-set bit planes (bits 0..3)

    int blk = blockIdx.x;
    int s   = blk & (NSTRIP - 1);
    int t2  = blk >> 1;
    int c   = t2 % NC;
    int b   = t2 / NC;
    int tid = threadIdx.x;
    int g0  = s * STRIP - HALO;

    const unsigned* mbase = g_bits + (size_t)(b * NC + c) * HH * WW;
    unsigned* t4 = g_t4 + (size_t)blk * IWORDS;
    for (int i = tid; i < NWORDS; i += TPB) {
        int g = g0 + (i >> 4);
        M[i]  = (g >= 0 && g < HH) ? mbase[(size_t)g * WW + (i & 15)] : 0u;
        Hb[i] = 0u;                        // stable 0 for never-written rows
    }
    for (int i = tid; i < 4 * IWORDS; i += TPB) T[i] = 0u;
    for (int i = tid; i < IWORDS; i += TPB) t4[i] = 0u;
    __syncthreads();

    unsigned mreg[NSLOT], G[NSLOT];
    bool inimg[NSLOT], act[NSLOT];
    bool allout = true;
#pragma unroll
    for (int j = 0; j < NSLOT; ++j) {
        int idx = j * TPB + tid;
        act[j] = (idx < NWORDS);
        mreg[j] = act[j] ? M[idx] : 0u;
        int g = g0 + (idx >> 4);
        inimg[j] = act[j] && (g >= 0) && (g < HH);
        allout &= !inimg[j];
    }
    bool done = allout;
    bool fixpend = false;

    for (int it = 0; it < 20; ++it) {
        // phase A: H = m | shl(m) | shr(m)
        if (!done) {
#pragma unroll
            for (int j = 0; j < NSLOT; ++j) {
                if (!act[j]) continue;
                int idx = j * TPB + tid;
                int k = idx & 15;
                unsigned m  = mreg[j];
                unsigned lw = (k > 0)  ? M[idx - 1] : 0u;
                unsigned rw = (k < 15) ? M[idx + 1] : 0u;
                unsigned g = __funnelshift_l(lw, m, 1) | __funnelshift_r(m, rw, 1);
                G[j] = g;
                Hb[idx] = m | g;
            }
        } else if (fixpend) {
#pragma unroll
            for (int j = 0; j < NSLOT; ++j)
                if (inimg[j]) Hb[j * TPB + tid] = mreg[j];
            fixpend = false;
        }
        __syncthreads();
        // phase B: nv = (H(up) | H(dn) | G) clamped outside the image
        int notsat = 0;
        if (!done) {
            unsigned sat = 0xFFFFFFFFu;
#pragma unroll
            for (int j = 0; j < NSLOT; ++j) {
                if (!act[j]) continue;
                int idx = j * TPB + tid;
                int r = idx >> 4;
                unsigned up = (r > 0)      ? Hb[idx - WW] : 0u;
                unsigned dn = (r < RB - 1) ? Hb[idx + WW] : 0u;
                unsigned nv = inimg[j] ? (up | dn | G[j]) : 0u;
                unsigned m  = mreg[j];
                bool interior = (r >= HALO) && (r < RB - HALO);
                if (interior) {
                    sat &= nv;
                    int pi = idx - HALO * WW;
                    if (it == 0) {
                        T[pi] = nv;        // first-set=1 for all of m_1
                    } else {
                        unsigned nb = nv & ~m;
                        if (nb) {
                            int jv = it + 1;
                            if (jv & 1)  T[pi]              |= nb;
                            if (jv & 2)  T[IWORDS + pi]     |= nb;
                            if (jv & 4)  T[2 * IWORDS + pi] |= nb;
                            if (jv & 8)  T[3 * IWORDS + pi] |= nb;
                            if (jv & 16) t4[pi]             |= nb;
                        }
                    }
                }
                mreg[j] = nv;
                M[idx] = nv;
            }
            notsat = (int)(sat != 0xFFFFFFFFu);
            if (!notsat) { done = true; fixpend = true; }
        }
        int any = __syncthreads_or(notsat);
        if (!any) break;   // all interior words saturated == fixed point
    }

    // finalize: byte = mf ? (first_set - m0bit) : 20 ; coalesced u32 stores
    unsigned* obase = (unsigned*)(g_dist + ((size_t)(b * NC + c) * HH + s * STRIP) * WIDTH);
    const unsigned* m0base = mbase + (size_t)(s * STRIP) * WW;
    for (int q = tid; q < STRIP * WIDTH / 4; q += TPB) {
        int r  = q >> 7;
        int u  = q & 127;
        int w  = u >> 3;
        int jb = (u & 7) * 4;
        int pi = r * WW + w;
        unsigned mf = M[(r + HALO) * WW + w];
        unsigned m0 = __ldg(m0base + r * WW + w);
        unsigned t0 = T[pi], t1 = T[IWORDS + pi], t2p = T[2 * IWORDS + pi],
                 t3 = T[3 * IWORDS + pi], tt4 = t4[pi];
        unsigned out = 0;
#pragma unroll
        for (int jj = 0; jj < 4; ++jj) {
            int j = jb + jj;
            int jset = (int)((t0 >> j) & 1u) + (int)(((t1 >> j) & 1u) << 1)
                     + (int)(((t2p >> j) & 1u) << 2) + (int)(((t3 >> j) & 1u) << 3)
                     + (int)(((tt4 >> j) & 1u) << 4);
            int v = ((mf >> j) & 1u) ? (jset - (int)((m0 >> j) & 1u)) : 20;
            out |= (unsigned)v << (jj * 8);
        }
        obase[q] = out;
    }
}

// K2: fused softmax + distance dot (4 px/thread, MUFU exp) + last-block-done
// deterministic final reduction (fixed-order read of all partials).
__global__ void k_loss(const float* __restrict__ pred, float* __restrict__ out) {
    __shared__ float red[8];
    __shared__ bool amlast;
    int g   = blockIdx.x * 256 + threadIdx.x;   // pixel-quad index
    int b   = g >> 16;
    int hw  = (g & 65535) * 4;
    const float4* p  = (const float4*)(pred   + (size_t)b * NC * HW + hw);
    const uchar4* dp = (const uchar4*)(g_dist + (size_t)b * NC * HW + hw);
    float se0 = 0.f, se1 = 0.f, se2 = 0.f, se3 = 0.f;
    float sd0 = 0.f, sd1 = 0.f, sd2 = 0.f, sd3 = 0.f;
#pragma unroll
    for (int c = 0; c < NC; ++c) {
        float4 v = __ldg(p + (size_t)c * (HW / 4));
        uchar4 d = __ldg(dp + (size_t)c * (HW / 4));
        float e0 = __expf(v.x), e1 = __expf(v.y), e2 = __expf(v.z), e3 = __expf(v.w);
        se0 += e0; se1 += e1; se2 += e2; se3 += e3;
        sd0 = fmaf(e0, (float)d.x, sd0);
        sd1 = fmaf(e1, (float)d.y, sd1);
        sd2 = fmaf(e2, (float)d.z, sd2);
        sd3 = fmaf(e3, (float)d.w, sd3);
    }
    float acc = __fdividef(sd0, se0) + __fdividef(sd1, se1)
              + __fdividef(sd2, se2) + __fdividef(sd3, se3);
#pragma unroll
    for (int o = 16; o; o >>= 1) acc += __shfl_down_sync(0xffffffffu, acc, o);
    int tid = threadIdx.x;
    if ((tid & 31) == 0) red[tid >> 5] = acc;
    __syncthreads();
    if (tid < 8) {
        float x = red[tid];
#pragma unroll
        for (int o = 4; o; o >>= 1) x += __shfl_down_sync(0x000000ffu, x, o);
        if (tid == 0) g_part[blockIdx.x] = x;
    }
    // last-block-done: deterministic final reduction (fixed read order)
    if (tid == 0) {
        __threadfence();
        amlast = (atomicAdd(&g_ctr, 1u) == NB3 - 1);
    }
    __syncthreads();
    if (amlast) {
        __threadfence();
        float v = 0.f;
#pragma unroll
        for (int i = 0; i < NB3 / 256; ++i) v += g_part[tid + i * 256];
#pragma unroll
        for (int o = 16; o; o >>= 1) v += __shfl_down_sync(0xffffffffu, v, o);
        if ((tid & 31) == 0) red[tid >> 5] = v;
        __syncthreads();
        if (tid < 8) {
            float x = red[tid];
#pragma unroll
            for (int o = 4; o; o >>= 1) x += __shfl_down_sync(0x000000ffu, x, o);
            if (tid == 0) {
                out[0] = x * (1.0f / ((float)BB * NC * HW));
                g_ctr = 0;                 // reset for next graph replay
            }
        }
    }
}

extern "C" void kernel_launch(void* const* d_in, const int* in_sizes, int n_in,
                              void* d_out, int out_size) {
    (void)in_sizes; (void)n_in; (void)out_size;
    const float* pred = (const float*)d_in[0];
    const int*   tgt  = (const int*)d_in[1];

    cudaFuncSetAttribute(k_dilate, cudaFuncAttributeMaxDynamicSharedMemorySize, SMEMSZ);

    k_bits<<<8192, 256>>>(tgt);
    k_dilate<<<NBLK, TPB, SMEMSZ>>>();
    k_loss<<<NB3, 256>>>(pred, (float*)d_out);
}